// round 1
// baseline (speedup 1.0000x reference)
#include <cuda_runtime.h>

#define VOCAB 65
#define NEMBD 32
#define HEAD  16
#define TBLK  8

// ---------------- precomputed tables (device globals; no allocation) --------
__device__ float g_Kt[VOCAB*HEAD], g_Qt[VOCAB*HEAD], g_Vt[VOCAB*HEAD];
__device__ float g_Kp[TBLK*HEAD],  g_Qp[TBLK*HEAD],  g_Vp[TBLK*HEAD];
__device__ float g_QKtt[VOCAB*VOCAB], g_QKtp[VOCAB*TBLK];
__device__ float g_QKpt[TBLK*VOCAB],  g_QKpp[TBLK*TBLK];
__device__ float g_Lt[VOCAB*VOCAB],   g_Lp[TBLK*VOCAB];
__device__ double g_loss;

// ---------------- setup kernel 1: token/pos projections ---------------------
__global__ void setup1(const float* __restrict__ tok, const float* __restrict__ pos,
                       const float* __restrict__ Wk, const float* __restrict__ bk,
                       const float* __restrict__ Wq, const float* __restrict__ bq,
                       const float* __restrict__ Wv, const float* __restrict__ bv) {
    int tid = blockIdx.x * blockDim.x + threadIdx.x;
    int stride = gridDim.x * blockDim.x;
    if (tid == 0) g_loss = 0.0;
    for (int i = tid; i < VOCAB*HEAD; i += stride) {
        int v = i / HEAD, h = i % HEAD;
        float sk = 0.f, sq = 0.f, sv = 0.f;
        #pragma unroll
        for (int c = 0; c < NEMBD; c++) {
            float x = tok[v*NEMBD + c];
            sk += x * Wk[c*HEAD + h];
            sq += x * Wq[c*HEAD + h];
            sv += x * Wv[c*HEAD + h];
        }
        g_Kt[i] = sk; g_Qt[i] = sq; g_Vt[i] = sv;
    }
    for (int i = tid; i < TBLK*HEAD; i += stride) {
        int t = i / HEAD, h = i % HEAD;
        float sk = bk[h], sq = bq[h], sv = bv[h];
        #pragma unroll
        for (int c = 0; c < NEMBD; c++) {
            float x = pos[t*NEMBD + c];
            sk += x * Wk[c*HEAD + h];
            sq += x * Wq[c*HEAD + h];
            sv += x * Wv[c*HEAD + h];
        }
        g_Kp[i] = sk; g_Qp[i] = sq; g_Vp[i] = sv;
    }
}

// ---------------- setup kernel 2: pair tables + LM-head tables --------------
__global__ void setup2(const float* __restrict__ Wlm) {
    int tid = blockIdx.x * blockDim.x + threadIdx.x;
    int stride = gridDim.x * blockDim.x;
    const float scale = 0.25f;  // HEAD^-0.5
    for (int i = tid; i < VOCAB*VOCAB; i += stride) {
        int a = i / VOCAB, b = i % VOCAB;
        float s = 0.f, l = 0.f;
        #pragma unroll
        for (int h = 0; h < HEAD; h++) {
            s += g_Qt[a*HEAD + h] * g_Kt[b*HEAD + h];
            l += g_Vt[a*HEAD + h] * Wlm[h*VOCAB + b];
        }
        g_QKtt[i] = scale * s;
        g_Lt[i]   = l;
    }
    for (int i = tid; i < VOCAB*TBLK; i += stride) {
        int a = i / TBLK, s2 = i % TBLK;
        float s = 0.f;
        #pragma unroll
        for (int h = 0; h < HEAD; h++) s += g_Qt[a*HEAD + h] * g_Kp[s2*HEAD + h];
        g_QKtp[i] = scale * s;
    }
    for (int i = tid; i < TBLK*VOCAB; i += stride) {
        int t = i / VOCAB, b = i % VOCAB;
        float s = 0.f, l = 0.f;
        #pragma unroll
        for (int h = 0; h < HEAD; h++) {
            s += g_Qp[t*HEAD + h] * g_Kt[b*HEAD + h];
            l += g_Vp[t*HEAD + h] * Wlm[h*VOCAB + b];
        }
        g_QKpt[i] = scale * s;
        g_Lp[i]   = l;
    }
    for (int i = tid; i < TBLK*TBLK; i += stride) {
        int t = i / TBLK, s2 = i % TBLK;
        float s = 0.f;
        #pragma unroll
        for (int h = 0; h < HEAD; h++) s += g_Qp[t*HEAD + h] * g_Kp[s2*HEAD + h];
        g_QKpp[i] = scale * s;
    }
}

// ---------------- main kernel: one warp per batch, persistent blocks --------
// smem layout (floats):
#define OFF_QKTT 0
#define OFF_LT   4225
#define OFF_QKTP 8450
#define OFF_QKPT 8970
#define OFF_QKPP 9490
#define OFF_LP   9554
#define OFF_BLM  10074
#define OFF_WARP 10144            // padded, 16B aligned
#define WARP_FLOATS 1120          // ids(8i)+tgs(8i)+wei(64)+Vl(520)+Lg(520)
#define NWARPS 8
#define SMEM_FLOATS (OFF_WARP + NWARPS*WARP_FLOATS)
#define SMEM_BYTES  (SMEM_FLOATS*4)

__global__ void __launch_bounds__(256)
main_kernel(const int* __restrict__ idx, const int* __restrict__ targets,
            const float* __restrict__ blm, float* __restrict__ out,
            int Bsz, int ngroups) {
    extern __shared__ float sm[];
    const int tid = threadIdx.x, lane = tid & 31, wid = tid >> 5;

    // cooperative table load (once per block; blocks are persistent)
    for (int i = tid; i < 4225; i += 256) {
        sm[OFF_QKTT + i] = g_QKtt[i];
        sm[OFF_LT   + i] = g_Lt[i];
    }
    for (int i = tid; i < 520; i += 256) {
        sm[OFF_QKTP + i] = g_QKtp[i];
        sm[OFF_QKPT + i] = g_QKpt[i];
        sm[OFF_LP   + i] = g_Lp[i];
    }
    if (tid < 64)    sm[OFF_QKPP + tid] = g_QKpp[tid];
    if (tid < VOCAB) sm[OFF_BLM  + tid] = blm[tid];
    __syncthreads();

    const float* s_QKtt = sm + OFF_QKTT;
    const float* s_Lt   = sm + OFF_LT;
    const float* s_QKtp = sm + OFF_QKTP;
    const float* s_QKpt = sm + OFF_QKPT;
    const float* s_QKpp = sm + OFF_QKPP;
    const float* s_Lp   = sm + OFF_LP;
    const float* s_blm  = sm + OFF_BLM;

    float* W   = sm + OFF_WARP + wid * WARP_FLOATS;
    int*   ids = (int*)W;
    int*   tgs = ids + 8;
    float* wei = W + 16;
    float* Vl  = W + 80;
    float* Lg  = W + 600;

    double lacc = 0.0;

    for (int g = blockIdx.x; g < ngroups; g += gridDim.x) {
        int b = g * NWARPS + wid;
        if (b < Bsz) {
            // ---- load token ids / targets for this batch row ----
            if (lane < TBLK) {
                ids[lane] = idx[b*TBLK + lane];
                tgs[lane] = targets[b*TBLK + lane];
            }
            __syncwarp();

            // ---- stage A: attention weights, softmax over QUERY axis (t),
            //      per key-column s (lane s<8 owns column s) ----
            if (lane < TBLK) {
                const int s = lane, as = ids[s];
                float e[TBLK];
                float m = -1e30f;
                #pragma unroll
                for (int t = 0; t < TBLK; t++) {
                    int at = ids[t];
                    float w = s_QKtt[at*VOCAB + as] + s_QKtp[at*TBLK + s]
                            + s_QKpt[t*VOCAB + as]  + s_QKpp[t*TBLK + s];
                    e[t] = (t >= s) ? w : -1e30f;
                    m = fmaxf(m, e[t]);
                }
                float sum = 0.f;
                #pragma unroll
                for (int t = 0; t < TBLK; t++) {
                    float x = __expf(e[t] - m);   // masked entries underflow to 0
                    e[t] = x;
                    sum += x;
                }
                float inv = 1.0f / sum;
                #pragma unroll
                for (int t = 0; t < TBLK; t++)
                    wei[t*TBLK + s] = (t >= s) ? e[t] * inv : 0.0f;
            }
            __syncwarp();

            // ---- stage B: per-key-row LM contributions Vl[s][v] ----
            for (int i = lane; i < TBLK*VOCAB; i += 32) {
                int s = i / VOCAB, v = i - s*VOCAB;
                Vl[i] = s_Lt[ids[s]*VOCAB + v] + s_Lp[i];
            }
            __syncwarp();

            // ---- stage C: logits[t][v] = blm[v] + sum_s wei[t][s]*Vl[s][v] ----
            for (int i = lane; i < TBLK*VOCAB; i += 32) {
                int t = i / VOCAB, v = i - t*VOCAB;
                const float* wrow = wei + t*TBLK;
                float acc = s_blm[v];
                #pragma unroll
                for (int s = 0; s < TBLK; s++)       // wei==0 for s>t
                    acc += wrow[s] * Vl[s*VOCAB + v];
                Lg[i] = acc;
            }
            __syncwarp();

            // ---- stage D: coalesced float4 write (520 floats = 130 float4) ----
            {
                float4* o4 = (float4*)(out + (size_t)b * (TBLK*VOCAB));
                const float4* l4 = (const float4*)Lg;
                for (int j = lane; j < (TBLK*VOCAB)/4; j += 32)
                    o4[j] = l4[j];
            }

            // ---- stage E: cross-entropy term (4 lanes per t) ----
            {
                int t = lane >> 2, sub = lane & 3;
                const float* row = Lg + t*VOCAB;
                float m = -1e30f;
                for (int v = sub; v < VOCAB; v += 4) m = fmaxf(m, row[v]);
                m = fmaxf(m, __shfl_xor_sync(0xffffffffu, m, 1));
                m = fmaxf(m, __shfl_xor_sync(0xffffffffu, m, 2));
                float s = 0.f;
                for (int v = sub; v < VOCAB; v += 4) s += __expf(row[v] - m);
                s += __shfl_xor_sync(0xffffffffu, s, 1);
                s += __shfl_xor_sync(0xffffffffu, s, 2);
                if (sub == 0)
                    lacc += (double)((m + __logf(s)) - row[tgs[t]]);
            }
        }
        __syncwarp();   // protect ids/Lg before next iteration overwrites
    }

    // warp-reduce the double loss accumulator, one atomic per warp
    #pragma unroll
    for (int off = 16; off > 0; off >>= 1)
        lacc += __shfl_down_sync(0xffffffffu, lacc, off);
    if (lane == 0) atomicAdd(&g_loss, lacc);
}

__global__ void finalize_kernel(float* __restrict__ out, long long n_logits, double invN) {
    out[n_logits] = (float)(g_loss * invN);
}

// ---------------- launch -----------------------------------------------------
extern "C" void kernel_launch(void* const* d_in, const int* in_sizes, int n_in,
                              void* d_out, int out_size) {
    const int*   idx  = (const int*)  d_in[0];
    const int*   tgt  = (const int*)  d_in[1];
    const float* tok  = (const float*)d_in[2];
    const float* pos  = (const float*)d_in[3];
    const float* Wk   = (const float*)d_in[4];
    const float* bk   = (const float*)d_in[5];
    const float* Wq   = (const float*)d_in[6];
    const float* bq   = (const float*)d_in[7];
    const float* Wv   = (const float*)d_in[8];
    const float* bv   = (const float*)d_in[9];
    const float* Wlm  = (const float*)d_in[10];
    const float* blm  = (const float*)d_in[11];

    int Bsz = in_sizes[0] / TBLK;
    int ngroups = (Bsz + NWARPS - 1) / NWARPS;

    setup1<<<4, 256>>>(tok, pos, Wk, bk, Wq, bq, Wv, bv);
    setup2<<<16, 256>>>(Wlm);

    cudaFuncSetAttribute(main_kernel, cudaFuncAttributeMaxDynamicSharedMemorySize, SMEM_BYTES);
    int grid = 304;                 // 152 SMs * 2 resident blocks, persistent
    main_kernel<<<grid, 256, SMEM_BYTES>>>(idx, tgt, blm, (float*)d_out, Bsz, ngroups);

    long long n_logits = (long long)Bsz * TBLK * VOCAB;
    finalize_kernel<<<1, 1>>>((float*)d_out, n_logits, 1.0 / ((double)Bsz * TBLK));
}